// round 17
// baseline (speedup 1.0000x reference)
#include <cuda_runtime.h>

#define NE_MAX 500000
#define NRELS 256
#define DIM 256
#define NBUCKETS 13            // node >> 14 for N_NODES=200000
#define NKEYS (NBUCKETS * NRELS)   // 3328 bins
#define SLAB_CAP 2048          // items per bin (avg ~300; huge safety margin)
#define KSPLIT 4

typedef unsigned int u32;

// ---- scratch (device globals; zero at module load) ----
// Invariant: g_bincnt == 0 at entry of every kernel_launch call.
// finalize_kernel restores it after consuming the counts.
__device__ int   g_bincnt[NKEYS];                   // items per (bucket,rel)
__device__ u32   g_slab[NKEYS * SLAB_CAP];          // node(18) | which(1)<<18
__device__ float g_AsumB[NBUCKETS][2 * NRELS * DIM]; // per-bucket partial sums (6.8MB)
// A: rows 0-255 src_avg, 256-511 dst_avg, 512-767 h_src, 768-1023 h_dst
__device__ float g_A[1024 * DIM];
// G partials: [ksplit][1024][768]; rows <512 use W_ih, rows >=512 use W_hh
__device__ float g_Gp[KSPLIT][1024 * 768];

// ------- phase 1: scatter items into per-bin slabs (bump allocation) -------
// 4 edges per thread -> 8 independent atomic+store chains in flight.
__global__ void __launch_bounds__(256) scatter_kernel(const int* __restrict__ src,
                                                      const int* __restrict__ dst,
                                                      const int* __restrict__ rel, int n) {
    int beg = blockIdx.x * (256 * 4) + threadIdx.x;
    int s[4], d[4], r[4];
    bool ok[4];
#pragma unroll
    for (int j = 0; j < 4; j++) {
        int i = beg + j * 256;           // coalesced
        ok[j] = (i < n);
        if (ok[j]) { s[j] = src[i]; d[j] = dst[i]; r[j] = rel[i]; }
    }
    int ks[4], kd[4], os[4], od[4];
#pragma unroll
    for (int j = 0; j < 4; j++) {        // 8 independent atomics back-to-back
        if (ok[j]) {
            ks[j] = (int)(((u32)s[j] >> 14) * NRELS + (u32)r[j]);
            kd[j] = (int)(((u32)d[j] >> 14) * NRELS + (u32)r[j]);
            os[j] = atomicAdd(&g_bincnt[ks[j]], 1);
            od[j] = atomicAdd(&g_bincnt[kd[j]], 1);
        }
    }
#pragma unroll
    for (int j = 0; j < 4; j++) {
        if (ok[j]) {
            if (os[j] < SLAB_CAP) g_slab[(size_t)ks[j] * SLAB_CAP + os[j]] = (u32)s[j];
            if (od[j] < SLAB_CAP) g_slab[(size_t)kd[j] * SLAB_CAP + od[j]] = (u32)d[j] | (1u << 18);
        }
    }
}

// ------- phase 2: one block per bin; accumulate, combine, plain store -------
__global__ void __launch_bounds__(256) reduce_kernel(const float* __restrict__ emb) {
    int key    = blockIdx.x;            // 0..NKEYS-1
    int bucket = key >> 8;              // key / NRELS
    int rel    = key & 255;
    int cnt    = min(g_bincnt[key], SLAB_CAP);

    int t = threadIdx.x;
    int sub = t >> 6;                   // 4 item streams
    int l   = t & 63;
    int q   = l << 2;                   // float4 column

    const u32* bin = g_slab + (size_t)key * SLAB_CAP;

    float4 as = make_float4(0.f, 0.f, 0.f, 0.f);
    float4 ad = as;

    int i = sub;
    // 2 items in flight per stream (8 gathers per 256-thread block iteration)
    for (; i + 4 < cnt; i += 8) {
        u32 p0 = bin[i];                // uniform per stream (broadcast load)
        u32 p1 = bin[i + 4];
        float4 v0 = __ldg((const float4*)&emb[(p0 & 0x3FFFF) * DIM + q]);
        float4 v1 = __ldg((const float4*)&emb[(p1 & 0x3FFFF) * DIM + q]);
        if (p0 >> 18) { ad.x += v0.x; ad.y += v0.y; ad.z += v0.z; ad.w += v0.w; }
        else          { as.x += v0.x; as.y += v0.y; as.z += v0.z; as.w += v0.w; }
        if (p1 >> 18) { ad.x += v1.x; ad.y += v1.y; ad.z += v1.z; ad.w += v1.w; }
        else          { as.x += v1.x; as.y += v1.y; as.z += v1.z; as.w += v1.w; }
    }
    for (; i < cnt; i += 4) {
        u32 p = bin[i];
        float4 v = __ldg((const float4*)&emb[(p & 0x3FFFF) * DIM + q]);
        if (p >> 18) { ad.x += v.x; ad.y += v.y; ad.z += v.z; ad.w += v.w; }
        else         { as.x += v.x; as.y += v.y; as.z += v.z; as.w += v.w; }
    }

    // combine 4 streams in smem, then exclusive-owner plain store
    __shared__ float4 s_s[4][64];
    __shared__ float4 s_d[4][64];
    s_s[sub][l] = as;
    s_d[sub][l] = ad;
    __syncthreads();
    if (sub == 0) {
        float4 a = s_s[0][l], b = s_s[1][l], c = s_s[2][l], e = s_s[3][l];
        a.x += b.x + c.x + e.x; a.y += b.y + c.y + e.y;
        a.z += b.z + c.z + e.z; a.w += b.w + c.w + e.w;
        float4 f = s_d[0][l], g = s_d[1][l], h = s_d[2][l], k = s_d[3][l];
        f.x += g.x + h.x + k.x; f.y += g.y + h.y + k.y;
        f.z += g.z + h.z + k.z; f.w += g.w + h.w + k.w;
        *(float4*)&g_AsumB[bucket][rel * DIM + q]           = a;
        *(float4*)&g_AsumB[bucket][(NRELS + rel) * DIM + q] = f;
    }
}

// ------- phase 3: sum buckets, divide, unpack h, restore bincnt=0 -------
// grid 256 (one block per rel), 128 threads (one float4 output per thread).
__global__ void __launch_bounds__(128) finalize_kernel(const float* __restrict__ dyn) {
    int r = blockIdx.x, t = threadIdx.x;
    int half = t >> 6;           // 0 = src row, 1 = dst row
    int c4   = (t & 63) << 2;    // float column

    float4 acc = make_float4(0.f, 0.f, 0.f, 0.f);
    int items = 0;
#pragma unroll
    for (int b = 0; b < NBUCKETS; b++) {
        items += g_bincnt[(b << 8) + r];
        float4 v = *(const float4*)&g_AsumB[b][(half * NRELS + r) * DIM + c4];
        acc.x += v.x; acc.y += v.y; acc.z += v.z; acc.w += v.w;
    }
    __syncthreads();             // all reads of g_bincnt done before restore
    if (t < NBUCKETS) g_bincnt[(t << 8) + r] = 0;   // invariant for next replay

    int cnt = items >> 1;        // (src+dst items) / 2 = edges for this rel
    float inv = 1.f / (float)(cnt > 0 ? cnt : 1);
    acc.x *= inv; acc.y *= inv; acc.z *= inv; acc.w *= inv;
    *(float4*)&g_A[(half * NRELS + r) * DIM + c4] = acc;

    // unpack dyn [r][0][d][k] (k innermost): float4 at r*512 + 4t covers
    // (d=2t,k=0),(d=2t,k=1),(d=2t+1,k=0),(d=2t+1,k=1)
    float4 dv = *(const float4*)&dyn[r * 512 + t * 4];
    g_A[(512 + r) * DIM + 2 * t]     = dv.x;   // h_src d=2t
    g_A[(768 + r) * DIM + 2 * t]     = dv.y;   // h_dst d=2t
    g_A[(512 + r) * DIM + 2 * t + 1] = dv.z;   // h_src d=2t+1
    g_A[(768 + r) * DIM + 2 * t + 1] = dv.w;   // h_dst d=2t+1
}

// ---- phase 4: GEMM  Gp[z] = A[:, z*64:(z+1)*64] @ Wsel[:, same]^T ----
// Tile 64(M) x 64(N) x 16(K); K split in 4; grid (12, 16, 4) = 768 blocks.
// Prefetch double-buffer: next k-tile's LDG overlaps current FMA loop.
#define TM 64
#define TN 64
#define TK 16
#define KCHUNK (256 / KSPLIT)   // 64
__global__ void __launch_bounds__(256) gemm_kernel(const float* __restrict__ Wih,
                                                   const float* __restrict__ Whh) {
    __shared__ float As[TK][TM + 4];
    __shared__ float Bs[TK][TN + 4];
    int bm = blockIdx.y, bn = blockIdx.x, bz = blockIdx.z;
    const float* Wsel = (bm < 8) ? Wih : Whh;
    int kbeg = bz * KCHUNK;

    int tid = threadIdx.x;
    int tx = tid & 15;
    int ty = tid >> 4;
    int lrow  = tid >> 2;
    int lcol4 = (tid & 3) * 4;

    const float* Aptr = g_A  + (bm * TM + lrow) * 256 + lcol4 + kbeg;
    const float* Bptr = Wsel + (bn * TN + lrow) * 256 + lcol4 + kbeg;

    float c[4][4] = {};

    float4 a4 = *(const float4*)(Aptr);
    float4 b4 = *(const float4*)(Bptr);

    for (int k0 = 0; k0 < KCHUNK; k0 += TK) {
        As[lcol4 + 0][lrow] = a4.x;
        As[lcol4 + 1][lrow] = a4.y;
        As[lcol4 + 2][lrow] = a4.z;
        As[lcol4 + 3][lrow] = a4.w;
        Bs[lcol4 + 0][lrow] = b4.x;
        Bs[lcol4 + 1][lrow] = b4.y;
        Bs[lcol4 + 2][lrow] = b4.z;
        Bs[lcol4 + 3][lrow] = b4.w;
        __syncthreads();

        // prefetch next k-tile while computing this one
        float4 a4n = a4, b4n = b4;
        if (k0 + TK < KCHUNK) {
            a4n = *(const float4*)(Aptr + k0 + TK);
            b4n = *(const float4*)(Bptr + k0 + TK);
        }

#pragma unroll
        for (int kk = 0; kk < TK; kk++) {
            float4 av = *(const float4*)&As[kk][ty * 4];
            float4 bv = *(const float4*)&Bs[kk][tx * 4];
            c[0][0] += av.x * bv.x; c[0][1] += av.x * bv.y; c[0][2] += av.x * bv.z; c[0][3] += av.x * bv.w;
            c[1][0] += av.y * bv.x; c[1][1] += av.y * bv.y; c[1][2] += av.y * bv.z; c[1][3] += av.y * bv.w;
            c[2][0] += av.z * bv.x; c[2][1] += av.z * bv.y; c[2][2] += av.z * bv.z; c[2][3] += av.z * bv.w;
            c[3][0] += av.w * bv.x; c[3][1] += av.w * bv.y; c[3][2] += av.w * bv.z; c[3][3] += av.w * bv.w;
        }
        __syncthreads();
        a4 = a4n;
        b4 = b4n;
    }

#pragma unroll
    for (int i = 0; i < 4; i++) {
        int row = bm * TM + ty * 4 + i;
        int col = bn * TN + tx * 4;
        float4 v = make_float4(c[i][0], c[i][1], c[i][2], c[i][3]);
        *(float4*)&g_Gp[bz][row * 768 + col] = v;
    }
}

// ---------------- phase 5: GRU gates + output (sums K-split partials) --------
__global__ void gate_kernel(const float* __restrict__ bih,
                            const float* __restrict__ bhh,
                            float* __restrict__ out) {
    int r = blockIdx.x;
    int d = threadIdx.x;

    float bir = bih[d], biz = bih[256 + d], bin_ = bih[512 + d];
    float bhr = bhh[d], bhz = bhh[256 + d], bhn = bhh[512 + d];

#pragma unroll
    for (int k = 0; k < 2; k++) {   // 0 = src, 1 = dst
        int xrow = k * 256 + r;
        int hrow = 512 + k * 256 + r;
        float ir = bir, iz = biz, in_ = bin_;
        float hr = bhr, hz = bhz, hn = bhn;
#pragma unroll
        for (int z = 0; z < KSPLIT; z++) {
            ir  += g_Gp[z][xrow * 768 + d];
            iz  += g_Gp[z][xrow * 768 + 256 + d];
            in_ += g_Gp[z][xrow * 768 + 512 + d];
            hr  += g_Gp[z][hrow * 768 + d];
            hz  += g_Gp[z][hrow * 768 + 256 + d];
            hn  += g_Gp[z][hrow * 768 + 512 + d];
        }
        float h = g_A[hrow * DIM + d];

        float rg = 1.f / (1.f + expf(-(ir + hr)));
        float z  = 1.f / (1.f + expf(-(iz + hz)));
        float nv = tanhf(in_ + rg * hn);
        out[r * (DIM * 2) + d * 2 + k] = (1.f - z) * nv + z * h;
    }
}

extern "C" void kernel_launch(void* const* d_in, const int* in_sizes, int n_in,
                              void* d_out, int out_size) {
    const int*   src = (const int*)d_in[0];
    const int*   dst = (const int*)d_in[1];
    const int*   rel = (const int*)d_in[2];
    const float* emb = (const float*)d_in[3];
    const float* dyn = (const float*)d_in[4];
    const float* Wih = (const float*)d_in[5];
    const float* Whh = (const float*)d_in[6];
    const float* bih = (const float*)d_in[7];
    const float* bhh = (const float*)d_in[8];
    float* out = (float*)d_out;
    int n = in_sizes[0];

    int nbS = (n + 1024 - 1) / 1024;
    scatter_kernel<<<nbS, 256>>>(src, dst, rel, n);
    reduce_kernel<<<NKEYS, 256>>>(emb);
    finalize_kernel<<<256, 128>>>(dyn);
    gemm_kernel<<<dim3(12, 16, KSPLIT), 256>>>(Wih, Whh);
    gate_kernel<<<256, 256>>>(bih, bhh, out);
}